// round 14
// baseline (speedup 1.0000x reference)
#include <cuda_runtime.h>
#include <cuda_fp16.h>
#include <cstdint>

#define DECAY 0.99f
#define ONE_MINUS_DECAY 0.01f
#define EPSF 1e-5f
#define D 512
#define KCODES 1024
#define NROWS 65536
#define BM 64
#define ROWTILES (NROWS / BM)    // 1024
#define NTILES 64                // 8 n-chunks * 8 k-tiles (BK=64)
#define A_BYTES 8192             // 64x64 fp16
#define B_BYTES 16384            // 128x64 fp16
#define STAGE_BYTES (A_BYTES + B_BYTES)      // 24576
#define NSTAGES 4
#define SMEM_TOTAL (NSTAGES * STAGE_BYTES)   // 98304 (dynamic)
#define MARGIN 0.05f
#define CH 64                    // rowlist entries per seg block

// ---------------- device scratch ----------------
__device__ unsigned g_xhi[NROWS * D / 2];     // fp16 pairs
__device__ unsigned g_bhi[KCODES * D / 2];    // fp16 pairs
__device__ float g_e2h[KCODES];   // 0.5*|e|^2
__device__ float g_embed_sum[KCODES * D];
__device__ int   g_ind[NROWS];
__device__ float g_cs[KCODES];
__device__ int   g_flag[NROWS];
__device__ int   g_nflag;
__device__ int   g_cnt[KCODES];
__device__ int   g_off[KCODES];
__device__ int   g_poslist[NROWS];
__device__ int   g_rowlist[NROWS];
__device__ unsigned long long g_best[NROWS];

// ---------------- PTX helpers ----------------
__device__ __forceinline__ uint32_t smem_u32(const void* p) {
    uint32_t a;
    asm("{ .reg .u64 t; cvta.to.shared.u64 t, %1; cvt.u32.u64 %0, t; }" : "=r"(a) : "l"(p));
    return a;
}
#define CP_ASYNC16(soff, gptr) \
    asm volatile("cp.async.cg.shared.global [%0], [%1], 16;" \
                 :: "r"(soff), "l"(__cvta_generic_to_global(gptr)))
#define CP_COMMIT() asm volatile("cp.async.commit_group;" ::: "memory")
#define CP_WAIT2() asm volatile("cp.async.wait_group 2;" ::: "memory")

#define LDMX4(r, addr) \
    asm volatile("ldmatrix.sync.aligned.m8n8.x4.shared.b16 {%0,%1,%2,%3}, [%4];" \
                 : "=r"((r)[0]), "=r"((r)[1]), "=r"((r)[2]), "=r"((r)[3]) : "r"(addr))

#define MMA_F16(c, a, b0, b1) \
    asm volatile("mma.sync.aligned.m16n8k16.row.col.f32.f16.f16.f32 " \
                 "{%0,%1,%2,%3}, {%4,%5,%6,%7}, {%8,%9}, {%0,%1,%2,%3};" \
                 : "+f"((c)[0]), "+f"((c)[1]), "+f"((c)[2]), "+f"((c)[3]) \
                 : "r"((a)[0]), "r"((a)[1]), "r"((a)[2]), "r"((a)[3]), "r"(b0), "r"(b1))

__device__ __forceinline__ unsigned pack2h(float a, float b) {
    __half2 h = __floats2half2_rn(a, b);
    return *(unsigned*)&h;
}

// ---------------- #1 prep B: convert embed fp16 + e2h + zero embed_sum/cnt ----------------
__global__ void prep_b(const float* __restrict__ embed) {
    int k = blockIdx.x;
    int t = threadIdx.x;       // 256 threads, one float2 each
    if (t == 0) g_cnt[k] = 0;
    if (k == 0 && t == 1) g_nflag = 0;
    ((float2*)g_embed_sum)[k * 256 + t] = make_float2(0.f, 0.f);
    float2 v = *(const float2*)(embed + (size_t)k * D + t * 2);
    g_bhi[k * 256 + t] = pack2h(v.x, v.y);
    float s = v.x * v.x + v.y * v.y;
#pragma unroll
    for (int off = 16; off; off >>= 1) s += __shfl_down_sync(0xffffffffu, s, off);
    __shared__ float sh[8];
    if ((t & 31) == 0) sh[t >> 5] = s;
    __syncthreads();
    if (t == 0) {
        float tot = 0.0f;
#pragma unroll
        for (int i = 0; i < 8; i++) tot += sh[i];
        g_e2h[k] = 0.5f * tot;
    }
}

// ---------------- #2/#3 convert x to fp16 (two halves so gemm is launch #4) ----------------
__global__ void convert_x(const float* __restrict__ x, int half) {
    const float4* x4 = (const float4*)x;
    uint2* o = (uint2*)g_xhi;
    size_t base = (size_t)half * (NROWS * D / 8);
    for (size_t i = (size_t)blockIdx.x * blockDim.x + threadIdx.x;
         i < (size_t)NROWS * D / 8; i += (size_t)gridDim.x * blockDim.x) {
        float4 v = x4[base + i];
        o[base + i] = make_uint2(pack2h(v.x, v.y), pack2h(v.z, v.w));
    }
}

// ---------------- #4 HMMA GEMM: double-buffered fragments, argmax state in smem ----------------
__global__ void __launch_bounds__(256, 2) gemm_hmma(float* __restrict__ eind) {
    extern __shared__ char smem[];
    __shared__ float s_best[4][256];
    __shared__ float s_second[4][256];
    __shared__ int   s_bidx[4][256];
    uint32_t sb = smem_u32(smem);
    const int tid = threadIdx.x;
    const int lane = tid & 31;
    const int warpM = (tid >> 5) >> 2;   // 0..1
    const int warpN = (tid >> 5) & 3;    // 0..3
    const int gid = lane >> 2, tig = lane & 3;
    const int rowTile = blockIdx.x;

    float acc[2][4][4];
#pragma unroll
    for (int s = 0; s < 4; s++) {
        s_best[s][tid] = -3.4e38f; s_second[s][tid] = -3.4e38f; s_bidx[s][tid] = 0;
    }

    auto issue = [&](int t) {
        int nc = t >> 3, kt = t & 7;
        uint32_t st = sb + (t & (NSTAGES - 1)) * STAGE_BYTES;
#pragma unroll
        for (int i = 0; i < 6; i++) {
            int idx = tid + i * 256;           // 0..1535; A: 0..511, B: 512..1535
            int isB = idx >= 512;
            int id2 = idx - (isB << 9);
            int row = id2 >> 3, g = id2 & 7;
            uint32_t soff = st + (isB ? A_BYTES : 0) + row * 128 + ((g ^ (row & 7)) << 4);
            size_t goff = isB
                ? ((size_t)(nc * 128 + row) * D + kt * 64 + g * 8) >> 1
                : ((size_t)(rowTile * BM + row) * D + kt * 64 + g * 8) >> 1;
            const unsigned* gp = isB ? g_bhi + goff : g_xhi + goff;
            CP_ASYNC16(soff, gp);
        }
        CP_COMMIT();
    };

    auto load_frags = [&](uint32_t st, int ks, uint32_t a[2][4], uint32_t b[2][4]) {
#pragma unroll
        for (int m = 0; m < 2; m++) {
            int r = warpM * 32 + m * 16 + (lane & 15);
            int kc = ks * 2 + (lane >> 4);
            uint32_t ad = st + r * 128 + ((kc ^ (r & 7)) << 4);
            LDMX4(a[m], ad);
        }
#pragma unroll
        for (int p = 0; p < 2; p++) {
            int grp = lane >> 3;
            int nt = p * 2 + (grp >> 1);
            int kc = ks * 2 + (grp & 1);
            int r = warpN * 32 + nt * 8 + (lane & 7);
            uint32_t ad = st + A_BYTES + r * 128 + ((kc ^ (r & 7)) << 4);
            LDMX4(b[p], ad);
        }
    };

    issue(0); issue(1); issue(2);

    for (int t = 0; t < NTILES; t++) {
        CP_WAIT2();
        __syncthreads();
        if (t + 3 < NTILES) issue(t + 3); else CP_COMMIT();

        if ((t & 7) == 0) {
#pragma unroll
            for (int m = 0; m < 2; m++)
#pragma unroll
                for (int n = 0; n < 4; n++)
#pragma unroll
                    for (int j = 0; j < 4; j++) acc[m][n][j] = 0.0f;
        }

        uint32_t st = sb + (t & (NSTAGES - 1)) * STAGE_BYTES;
        uint32_t ah[2][2][4], bh[2][2][4];
        load_frags(st, 0, ah[0], bh[0]);
#pragma unroll
        for (int ks = 0; ks < 4; ks++) {
            int cur = ks & 1;
            if (ks < 3) load_frags(st, ks + 1, ah[cur ^ 1], bh[cur ^ 1]);
#pragma unroll
            for (int m = 0; m < 2; m++)
#pragma unroll
                for (int n = 0; n < 4; n++) {
                    uint32_t b0h = bh[cur][n >> 1][(n & 1) * 2];
                    uint32_t b1h = bh[cur][n >> 1][(n & 1) * 2 + 1];
                    MMA_F16(acc[m][n], ah[cur][m], b0h, b1h);
                }
        }

        if ((t & 7) == 7) {
            int nc = t >> 3;
            float lb[4], ls[4];
            int li[4];
#pragma unroll
            for (int s = 0; s < 4; s++) { lb[s] = s_best[s][tid]; ls[s] = s_second[s][tid]; li[s] = s_bidx[s][tid]; }
#pragma unroll
            for (int n = 0; n < 4; n++) {
                int col0 = nc * 128 + warpN * 32 + n * 8 + tig * 2;
                float e0 = __ldg(&g_e2h[col0]);
                float e1 = __ldg(&g_e2h[col0 + 1]);
#pragma unroll
                for (int m = 0; m < 2; m++)
#pragma unroll
                    for (int h = 0; h < 2; h++) {
                        int slot = m * 2 + h;
                        float s0 = acc[m][n][h * 2 + 0] - e0;
                        float s1 = acc[m][n][h * 2 + 1] - e1;
                        if (s0 > lb[slot]) { ls[slot] = lb[slot]; lb[slot] = s0; li[slot] = col0; }
                        else if (s0 > ls[slot]) ls[slot] = s0;
                        if (s1 > lb[slot]) { ls[slot] = lb[slot]; lb[slot] = s1; li[slot] = col0 + 1; }
                        else if (s1 > ls[slot]) ls[slot] = s1;
                    }
            }
#pragma unroll
            for (int s = 0; s < 4; s++) { s_best[s][tid] = lb[s]; s_second[s][tid] = ls[s]; s_bidx[s][tid] = li[s]; }
        }
    }

    __syncthreads();
    float* mb = (float*)smem;          // [64][4]
    float* ms = mb + 256;
    int*   mi = (int*)(ms + 256);
#pragma unroll
    for (int slot = 0; slot < 4; slot++) {
        float b = s_best[slot][tid], s = s_second[slot][tid];
        int i = s_bidx[slot][tid];
#pragma unroll
        for (int off = 1; off <= 2; off <<= 1) {
            float ob = __shfl_xor_sync(0xffffffffu, b, off);
            float os = __shfl_xor_sync(0xffffffffu, s, off);
            int   oi = __shfl_xor_sync(0xffffffffu, i, off);
            if (ob > b || (ob == b && oi < i)) { s = fmaxf(os, b); b = ob; i = oi; }
            else s = fmaxf(s, ob);
        }
        if (tig == 0) {
            int row = warpM * 32 + (slot >> 1) * 16 + gid + (slot & 1) * 8;
            mb[row * 4 + warpN] = b; ms[row * 4 + warpN] = s; mi[row * 4 + warpN] = i;
        }
    }
    __syncthreads();
    if (tid < BM) {
        int row = tid;
        float b = mb[row * 4], s = ms[row * 4];
        int i = mi[row * 4];
#pragma unroll
        for (int w = 1; w < 4; w++) {
            float ob = mb[row * 4 + w], os = ms[row * 4 + w];
            int oi = mi[row * 4 + w];
            if (ob > b || (ob == b && oi < i)) { s = fmaxf(os, b); b = ob; i = oi; }
            else s = fmaxf(s, ob);
        }
        int grow = rowTile * BM + row;
        g_ind[grow] = i;
        if (b - s < MARGIN) {
            g_best[grow] = 0ull;
            int p = atomicAdd(&g_nflag, 1);
            g_flag[p] = grow;
        } else {
            g_poslist[grow] = atomicAdd(&g_cnt[i], 1);
            eind[grow] = (float)i;
        }
    }
}

// ---------------- #5 exact fp32 rescue (R9/R13 version, measured 51us) ----------------
__global__ void __launch_bounds__(256) rescue(const float* __restrict__ x,
                                              const float* __restrict__ embed) {
    __shared__ float4 xs[128];   // the row, 512 floats
    int tid = threadIdx.x;
    int w = tid >> 5, lane = tid & 31;
    int nitems = g_nflag * 8;
    for (int it = blockIdx.x; it < nitems; it += gridDim.x) {
        int row = g_flag[it >> 3];
        int slice = it & 7;
        __syncthreads();
        if (tid < 128) xs[tid] = *((const float4*)(x + (size_t)row * D) + tid);
        __syncthreads();
        float best = -3.4e38f;
        int bc = 0;
#pragma unroll
        for (int i = 0; i < 16; i++) {
            int c = slice * 128 + w * 16 + i;
            const float4* ep = (const float4*)(embed + (size_t)c * D);
            float dot = 0.0f;
#pragma unroll
            for (int p = 0; p < 4; p++) {
                float4 e = __ldg(ep + lane + p * 32);
                float4 xv = xs[lane + p * 32];
                dot = fmaf(xv.x, e.x, fmaf(xv.y, e.y,
                       fmaf(xv.z, e.z, fmaf(xv.w, e.w, dot))));
            }
#pragma unroll
            for (int off = 16; off; off >>= 1)
                dot += __shfl_xor_sync(0xffffffffu, dot, off);
            if (lane == 0) {
                float s = dot - g_e2h[c];
                if (s > best) { best = s; bc = c; }
            }
        }
        if (lane == 0) {
            unsigned bits = __float_as_uint(best);
            unsigned mono = (bits & 0x80000000u) ? ~bits : (bits | 0x80000000u);
            unsigned long long u = ((unsigned long long)mono << 32) | (unsigned)(~bc);
            atomicMax(&g_best[row], u);
        }
    }
}

// ---------------- #6 rescue finalize + scan + ema_cs (single block) ----------------
__global__ void scan_counts(const float* __restrict__ cluster_size,
                            float* __restrict__ ncs_out,
                            float* __restrict__ eind) {
    int k = threadIdx.x;
    // phase 0: finalize flagged rows (deferred counting)
    int nf = g_nflag;
    for (int i = k; i < nf; i += 1024) {
        int row = g_flag[i];
        int kk = (int)(~(unsigned)(g_best[row] & 0xffffffffull)) & 1023;
        g_ind[row] = kk;
        g_poslist[row] = atomicAdd(&g_cnt[kk], 1);
        eind[row] = (float)kk;
    }
    __syncthreads();
    // phase 1: scan counts + laplace denominator
    __shared__ int s[1024];
    __shared__ float f[1024];
    int my = g_cnt[k];
    s[k] = my;
    __syncthreads();
#pragma unroll
    for (int off = 1; off < 1024; off <<= 1) {
        int v = (k >= off) ? s[k - off] : 0;
        __syncthreads();
        s[k] += v;
        __syncthreads();
    }
    g_off[k] = s[k] - my;
    float ncs = cluster_size[k] * DECAY + ONE_MINUS_DECAY * (float)my;
    ncs_out[k] = ncs;
    f[k] = ncs;
    __syncthreads();
#pragma unroll
    for (int st = 512; st > 0; st >>= 1) {
        if (k < st) f[k] += f[k + st];
        __syncthreads();
    }
    float n = f[0];
    g_cs[k] = (ncs + EPSF) / (n + (float)KCODES * EPSF) * n;
}

// ---------------- #7 fill rowlist ----------------
__global__ void fill_rowlist() {
    int row = blockIdx.x * blockDim.x + threadIdx.x;
    int k = g_ind[row];
    g_rowlist[g_off[k] + g_poslist[row]] = row;
}

// ---------------- #8 seg_quant: quant fill + segmented embed_sum fused ----------------
__global__ void __launch_bounds__(128) seg_quant(const float* __restrict__ x,
                                                 const float* __restrict__ embed,
                                                 float* __restrict__ quant) {
    __shared__ int rows[CH];
    __shared__ int codes[CH];
    int t = threadIdx.x;
    int j0 = blockIdx.x * CH;
    if (t < CH) {
        int r = g_rowlist[j0 + t];
        rows[t] = r;
        codes[t] = g_ind[r];
    }
    __syncthreads();
    float4 e = __ldg((const float4*)(embed + (size_t)codes[0] * D) + t);
    float4 acc = {0.f, 0.f, 0.f, 0.f};
#pragma unroll 4
    for (int j = 0; j < CH; j++) {
        if (j > 0 && codes[j] != codes[j - 1])
            e = __ldg((const float4*)(embed + (size_t)codes[j] * D) + t);
        *((float4*)(quant + (size_t)rows[j] * D) + t) = e;
        float4 v = __ldg((const float4*)(x + (size_t)rows[j] * D) + t);
        acc.x += v.x; acc.y += v.y; acc.z += v.z; acc.w += v.w;
        if (j == CH - 1 || codes[j + 1] != codes[j]) {
            float* es = g_embed_sum + (size_t)codes[j] * D + t * 4;
            atomicAdd(es + 0, acc.x);
            atomicAdd(es + 1, acc.y);
            atomicAdd(es + 2, acc.z);
            atomicAdd(es + 3, acc.w);
            acc = make_float4(0.f, 0.f, 0.f, 0.f);
        }
    }
}

// ---------------- #9 EMA embed (flat) ----------------
__global__ void __launch_bounds__(256) ema_embed(const float* __restrict__ embed_avg,
                                                 float* __restrict__ nea_out,
                                                 float* __restrict__ ne_out) {
    int i = blockIdx.x * 256 + threadIdx.x;   // over KCODES*D/4 float4
    int c = (i * 4) >> 9;
    float4 es = *((const float4*)g_embed_sum + i);
    float4 ea = __ldg((const float4*)embed_avg + i);
    float inv = 1.0f / g_cs[c];
    float4 nea, ne;
    nea.x = ea.x * DECAY + ONE_MINUS_DECAY * es.x; ne.x = nea.x * inv;
    nea.y = ea.y * DECAY + ONE_MINUS_DECAY * es.y; ne.y = nea.y * inv;
    nea.z = ea.z * DECAY + ONE_MINUS_DECAY * es.z; ne.z = nea.z * inv;
    nea.w = ea.w * DECAY + ONE_MINUS_DECAY * es.w; ne.w = nea.w * inv;
    ((float4*)nea_out)[i] = nea;
    ((float4*)ne_out)[i] = ne;
}

// ---------------- launch ----------------
extern "C" void kernel_launch(void* const* d_in, const int* in_sizes, int n_in,
                              void* d_out, int out_size) {
    const float* x = (const float*)d_in[0];
    const float* embed = (const float*)d_in[1];
    const float* cluster_size = (const float*)d_in[2];
    const float* embed_avg = (const float*)d_in[3];

    float* out = (float*)d_out;
    float* quant = out;
    float* eind  = quant + (size_t)NROWS * D;
    float* ncs   = eind + NROWS;
    float* nea   = ncs + KCODES;
    float* ne    = nea + (size_t)KCODES * D;

    cudaFuncSetAttribute(gemm_hmma, cudaFuncAttributeMaxDynamicSharedMemorySize, SMEM_TOTAL);

    prep_b<<<KCODES, 256>>>(embed);                      // #1
    convert_x<<<1024, 256>>>(x, 0);                      // #2
    convert_x<<<1024, 256>>>(x, 1);                      // #3
    gemm_hmma<<<ROWTILES, 256, SMEM_TOTAL>>>(eind);      // #4  <-- profile target
    rescue<<<4096, 256>>>(x, embed);                     // #5
    scan_counts<<<1, 1024>>>(cluster_size, ncs, eind);   // #6
    fill_rowlist<<<NROWS / 256, 256>>>();                // #7
    seg_quant<<<NROWS / CH, 128>>>(x, embed, quant);     // #8
    ema_embed<<<KCODES * D / 4 / 256, 256>>>(embed_avg, nea, ne);  // #9
}

// round 15
// speedup vs baseline: 1.0899x; 1.0899x over previous
#include <cuda_runtime.h>
#include <cuda_fp16.h>
#include <cstdint>

#define DECAY 0.99f
#define ONE_MINUS_DECAY 0.01f
#define EPSF 1e-5f
#define D 512
#define KCODES 1024
#define NROWS 65536
#define BM 64
#define ROWTILES (NROWS / BM)    // 1024
#define NTILES 64                // 8 n-chunks * 8 k-tiles (BK=64)
#define A_BYTES 8192             // 64x64 fp16
#define B_BYTES 16384            // 128x64 fp16
#define STAGE_BYTES (A_BYTES + B_BYTES)      // 24576
#define NSTAGES 4
#define SMEM_TOTAL (NSTAGES * STAGE_BYTES)   // 98304 (dynamic)
#define MARGIN 0.05f
#define CH 64                    // rowlist entries per seg block
#define RG 4                     // rescue rows per group

// ---------------- device scratch ----------------
__device__ unsigned g_xhi[NROWS * D / 2];     // fp16 pairs
__device__ unsigned g_bhi[KCODES * D / 2];    // fp16 pairs
__device__ float g_e2h[KCODES];   // 0.5*|e|^2
__device__ float g_embed_sum[KCODES * D];
__device__ int   g_ind[NROWS];
__device__ float g_cs[KCODES];
__device__ int   g_flag[NROWS];
__device__ int   g_nflag;
__device__ int   g_cnt[KCODES];
__device__ int   g_off[KCODES];
__device__ int   g_poslist[NROWS];
__device__ int   g_rowlist[NROWS];
__device__ unsigned long long g_best[NROWS];

// ---------------- PTX helpers ----------------
__device__ __forceinline__ uint32_t smem_u32(const void* p) {
    uint32_t a;
    asm("{ .reg .u64 t; cvta.to.shared.u64 t, %1; cvt.u32.u64 %0, t; }" : "=r"(a) : "l"(p));
    return a;
}
#define CP_ASYNC16(soff, gptr) \
    asm volatile("cp.async.cg.shared.global [%0], [%1], 16;" \
                 :: "r"(soff), "l"(__cvta_generic_to_global(gptr)))
#define CP_COMMIT() asm volatile("cp.async.commit_group;" ::: "memory")
#define CP_WAIT2() asm volatile("cp.async.wait_group 2;" ::: "memory")

#define LDMX4(r, addr) \
    asm volatile("ldmatrix.sync.aligned.m8n8.x4.shared.b16 {%0,%1,%2,%3}, [%4];" \
                 : "=r"((r)[0]), "=r"((r)[1]), "=r"((r)[2]), "=r"((r)[3]) : "r"(addr))

#define MMA_F16(c, a, b0, b1) \
    asm volatile("mma.sync.aligned.m16n8k16.row.col.f32.f16.f16.f32 " \
                 "{%0,%1,%2,%3}, {%4,%5,%6,%7}, {%8,%9}, {%0,%1,%2,%3};" \
                 : "+f"((c)[0]), "+f"((c)[1]), "+f"((c)[2]), "+f"((c)[3]) \
                 : "r"((a)[0]), "r"((a)[1]), "r"((a)[2]), "r"((a)[3]), "r"(b0), "r"(b1))

__device__ __forceinline__ unsigned pack2h(float a, float b) {
    __half2 h = __floats2half2_rn(a, b);
    return *(unsigned*)&h;
}

// ---------------- #1 prep B: convert embed fp16 + e2h + zero embed_sum/cnt ----------------
__global__ void prep_b(const float* __restrict__ embed) {
    int k = blockIdx.x;
    int t = threadIdx.x;       // 256 threads, one float2 each
    if (t == 0) g_cnt[k] = 0;
    if (k == 0 && t == 1) g_nflag = 0;
    ((float2*)g_embed_sum)[k * 256 + t] = make_float2(0.f, 0.f);
    float2 v = *(const float2*)(embed + (size_t)k * D + t * 2);
    g_bhi[k * 256 + t] = pack2h(v.x, v.y);
    float s = v.x * v.x + v.y * v.y;
#pragma unroll
    for (int off = 16; off; off >>= 1) s += __shfl_down_sync(0xffffffffu, s, off);
    __shared__ float sh[8];
    if ((t & 31) == 0) sh[t >> 5] = s;
    __syncthreads();
    if (t == 0) {
        float tot = 0.0f;
#pragma unroll
        for (int i = 0; i < 8; i++) tot += sh[i];
        g_e2h[k] = 0.5f * tot;
    }
}

// ---------------- #2 convert x to fp16 (grid-stride float4) ----------------
__global__ void convert_x(const float* __restrict__ x) {
    const float4* x4 = (const float4*)x;
    uint2* o = (uint2*)g_xhi;
    for (size_t i = (size_t)blockIdx.x * blockDim.x + threadIdx.x;
         i < (size_t)NROWS * D / 4; i += (size_t)gridDim.x * blockDim.x) {
        float4 v = x4[i];
        o[i] = make_uint2(pack2h(v.x, v.y), pack2h(v.z, v.w));
    }
}

// ---------------- #3 HMMA GEMM (R13 config: registers argmax, no frag dbuf) ----------------
__global__ void __launch_bounds__(256, 2) gemm_hmma(float* __restrict__ eind) {
    extern __shared__ char smem[];
    uint32_t sb = smem_u32(smem);
    const int tid = threadIdx.x;
    const int lane = tid & 31;
    const int warpM = (tid >> 5) >> 2;   // 0..1
    const int warpN = (tid >> 5) & 3;    // 0..3
    const int gid = lane >> 2, tig = lane & 3;
    const int rowTile = blockIdx.x;

    float acc[2][4][4];
    float best[4], second[4];
    int bidx[4];
#pragma unroll
    for (int s = 0; s < 4; s++) { best[s] = -3.4e38f; second[s] = -3.4e38f; bidx[s] = 0; }

    auto issue = [&](int t) {
        int nc = t >> 3, kt = t & 7;
        uint32_t st = sb + (t & (NSTAGES - 1)) * STAGE_BYTES;
#pragma unroll
        for (int i = 0; i < 6; i++) {
            int idx = tid + i * 256;           // 0..1535; A: 0..511, B: 512..1535
            int isB = idx >= 512;
            int id2 = idx - (isB << 9);
            int row = id2 >> 3, g = id2 & 7;
            uint32_t soff = st + (isB ? A_BYTES : 0) + row * 128 + ((g ^ (row & 7)) << 4);
            size_t goff = isB
                ? ((size_t)(nc * 128 + row) * D + kt * 64 + g * 8) >> 1
                : ((size_t)(rowTile * BM + row) * D + kt * 64 + g * 8) >> 1;
            const unsigned* gp = isB ? g_bhi + goff : g_xhi + goff;
            CP_ASYNC16(soff, gp);
        }
        CP_COMMIT();
    };

    issue(0); issue(1); issue(2);

    for (int t = 0; t < NTILES; t++) {
        CP_WAIT2();
        __syncthreads();
        if (t + 3 < NTILES) issue(t + 3); else CP_COMMIT();

        if ((t & 7) == 0) {
#pragma unroll
            for (int m = 0; m < 2; m++)
#pragma unroll
                for (int n = 0; n < 4; n++)
#pragma unroll
                    for (int j = 0; j < 4; j++) acc[m][n][j] = 0.0f;
        }

        uint32_t st = sb + (t & (NSTAGES - 1)) * STAGE_BYTES;
#pragma unroll
        for (int ks = 0; ks < 4; ks++) {
            uint32_t ah[2][4], bh[2][4];
#pragma unroll
            for (int m = 0; m < 2; m++) {
                int r = warpM * 32 + m * 16 + (lane & 15);
                int kc = ks * 2 + (lane >> 4);
                uint32_t a = st + r * 128 + ((kc ^ (r & 7)) << 4);
                LDMX4(ah[m], a);
            }
#pragma unroll
            for (int p = 0; p < 2; p++) {
                int grp = lane >> 3;
                int nt = p * 2 + (grp >> 1);
                int kc = ks * 2 + (grp & 1);
                int r = warpN * 32 + nt * 8 + (lane & 7);
                uint32_t a = st + A_BYTES + r * 128 + ((kc ^ (r & 7)) << 4);
                LDMX4(bh[p], a);
            }
#pragma unroll
            for (int m = 0; m < 2; m++)
#pragma unroll
                for (int n = 0; n < 4; n++) {
                    uint32_t b0h = bh[n >> 1][(n & 1) * 2], b1h = bh[n >> 1][(n & 1) * 2 + 1];
                    MMA_F16(acc[m][n], ah[m], b0h, b1h);
                }
        }

        if ((t & 7) == 7) {
            int nc = t >> 3;
#pragma unroll
            for (int n = 0; n < 4; n++) {
                int col0 = nc * 128 + warpN * 32 + n * 8 + tig * 2;
                float e0 = __ldg(&g_e2h[col0]);
                float e1 = __ldg(&g_e2h[col0 + 1]);
#pragma unroll
                for (int m = 0; m < 2; m++)
#pragma unroll
                    for (int h = 0; h < 2; h++) {
                        int slot = m * 2 + h;
                        float s0 = acc[m][n][h * 2 + 0] - e0;
                        float s1 = acc[m][n][h * 2 + 1] - e1;
                        if (s0 > best[slot]) { second[slot] = best[slot]; best[slot] = s0; bidx[slot] = col0; }
                        else if (s0 > second[slot]) second[slot] = s0;
                        if (s1 > best[slot]) { second[slot] = best[slot]; best[slot] = s1; bidx[slot] = col0 + 1; }
                        else if (s1 > second[slot]) second[slot] = s1;
                    }
            }
        }
    }

    __syncthreads();
    float* mb = (float*)smem;          // [64][4]
    float* ms = mb + 256;
    int*   mi = (int*)(ms + 256);
#pragma unroll
    for (int slot = 0; slot < 4; slot++) {
        float b = best[slot], s = second[slot];
        int i = bidx[slot];
#pragma unroll
        for (int off = 1; off <= 2; off <<= 1) {
            float ob = __shfl_xor_sync(0xffffffffu, b, off);
            float os = __shfl_xor_sync(0xffffffffu, s, off);
            int   oi = __shfl_xor_sync(0xffffffffu, i, off);
            if (ob > b || (ob == b && oi < i)) { s = fmaxf(os, b); b = ob; i = oi; }
            else s = fmaxf(s, ob);
        }
        if (tig == 0) {
            int row = warpM * 32 + (slot >> 1) * 16 + gid + (slot & 1) * 8;
            mb[row * 4 + warpN] = b; ms[row * 4 + warpN] = s; mi[row * 4 + warpN] = i;
        }
    }
    __syncthreads();
    if (tid < BM) {
        int row = tid;
        float b = mb[row * 4], s = ms[row * 4];
        int i = mi[row * 4];
#pragma unroll
        for (int w = 1; w < 4; w++) {
            float ob = mb[row * 4 + w], os = ms[row * 4 + w];
            int oi = mi[row * 4 + w];
            if (ob > b || (ob == b && oi < i)) { s = fmaxf(os, b); b = ob; i = oi; }
            else s = fmaxf(s, ob);
        }
        int grow = rowTile * BM + row;
        g_ind[grow] = i;
        if (b - s < MARGIN) {
            g_best[grow] = 0ull;
            int p = atomicAdd(&g_nflag, 1);
            g_flag[p] = grow;
        } else {
            g_poslist[grow] = atomicAdd(&g_cnt[i], 1);
            eind[grow] = (float)i;
        }
    }
}

// ---------------- #4 exact fp32 rescue: one item = (4-row group, 1/8 codebook) ----------------
__global__ void __launch_bounds__(256) rescue(const float* __restrict__ x,
                                              const float* __restrict__ embed) {
    __shared__ float4 xs[RG][128];     // 4 rows x 512 floats = 8KB
    int tid = threadIdx.x;
    int w = tid >> 5, lane = tid & 31;
    int nf = g_nflag;
    int nitems = ((nf + RG - 1) / RG) * 8;
    for (int it = blockIdx.x; it < nitems; it += gridDim.x) {
        int g = it >> 3, slice = it & 7;
        int cnt = min(RG, nf - g * RG);
        __syncthreads();
        for (int i = tid; i < cnt * 128; i += 256) {
            int r = i >> 7, j = i & 127;
            xs[r][j] = *((const float4*)(x + (size_t)g_flag[g * RG + r] * D) + j);
        }
        __syncthreads();
        float best = -3.4e38f;
        int bc = 0;
#pragma unroll
        for (int i = 0; i < 16; i++) {
            int c = slice * 128 + w * 16 + i;
            const float4* ep = (const float4*)(embed + (size_t)c * D);
            float acc[RG];
#pragma unroll
            for (int r = 0; r < RG; r++) acc[r] = 0.0f;
#pragma unroll
            for (int p = 0; p < 4; p++) {
                float4 e = __ldg(ep + lane + p * 32);
#pragma unroll
                for (int r = 0; r < RG; r++) {
                    float4 xv = xs[r][lane + p * 32];
                    acc[r] = fmaf(xv.x, e.x, fmaf(xv.y, e.y,
                              fmaf(xv.z, e.z, fmaf(xv.w, e.w, acc[r]))));
                }
            }
#pragma unroll
            for (int r = 0; r < RG; r++) {
#pragma unroll
                for (int off = 16; off; off >>= 1)
                    acc[r] += __shfl_xor_sync(0xffffffffu, acc[r], off);
            }
            if (lane < cnt) {
                float s = acc[lane] - g_e2h[c];
                if (s > best) { best = s; bc = c; }
            }
        }
        if (lane < cnt) {
            unsigned bits = __float_as_uint(best);
            unsigned mono = (bits & 0x80000000u) ? ~bits : (bits | 0x80000000u);
            unsigned long long u = ((unsigned long long)mono << 32) | (unsigned)(~bc);
            atomicMax(&g_best[g_flag[g * RG + lane]], u);
        }
    }
}

// ---------------- #5 rescue finalize + scan + ema_cs (single block) ----------------
__global__ void scan_counts(const float* __restrict__ cluster_size,
                            float* __restrict__ ncs_out,
                            float* __restrict__ eind) {
    int k = threadIdx.x;
    int nf = g_nflag;
    for (int i = k; i < nf; i += 1024) {
        int row = g_flag[i];
        int kk = (int)(~(unsigned)(g_best[row] & 0xffffffffull)) & 1023;
        g_ind[row] = kk;
        g_poslist[row] = atomicAdd(&g_cnt[kk], 1);
        eind[row] = (float)kk;
    }
    __syncthreads();
    __shared__ int s[1024];
    __shared__ float f[1024];
    int my = g_cnt[k];
    s[k] = my;
    __syncthreads();
#pragma unroll
    for (int off = 1; off < 1024; off <<= 1) {
        int v = (k >= off) ? s[k - off] : 0;
        __syncthreads();
        s[k] += v;
        __syncthreads();
    }
    g_off[k] = s[k] - my;
    float ncs = cluster_size[k] * DECAY + ONE_MINUS_DECAY * (float)my;
    ncs_out[k] = ncs;
    f[k] = ncs;
    __syncthreads();
#pragma unroll
    for (int st = 512; st > 0; st >>= 1) {
        if (k < st) f[k] += f[k + st];
        __syncthreads();
    }
    float n = f[0];
    g_cs[k] = (ncs + EPSF) / (n + (float)KCODES * EPSF) * n;
}

// ---------------- #6 fill rowlist ----------------
__global__ void fill_rowlist() {
    int row = blockIdx.x * blockDim.x + threadIdx.x;
    int k = g_ind[row];
    g_rowlist[g_off[k] + g_poslist[row]] = row;
}

// ---------------- #7 seg_quant: quant fill + segmented embed_sum fused ----------------
__global__ void __launch_bounds__(128) seg_quant(const float* __restrict__ x,
                                                 const float* __restrict__ embed,
                                                 float* __restrict__ quant) {
    __shared__ int rows[CH];
    __shared__ int codes[CH];
    int t = threadIdx.x;
    int j0 = blockIdx.x * CH;
    if (t < CH) {
        int r = g_rowlist[j0 + t];
        rows[t] = r;
        codes[t] = g_ind[r];
    }
    __syncthreads();
    float4 e = __ldg((const float4*)(embed + (size_t)codes[0] * D) + t);
    float4 acc = {0.f, 0.f, 0.f, 0.f};
#pragma unroll 4
    for (int j = 0; j < CH; j++) {
        if (j > 0 && codes[j] != codes[j - 1])
            e = __ldg((const float4*)(embed + (size_t)codes[j] * D) + t);
        *((float4*)(quant + (size_t)rows[j] * D) + t) = e;
        float4 v = __ldg((const float4*)(x + (size_t)rows[j] * D) + t);
        acc.x += v.x; acc.y += v.y; acc.z += v.z; acc.w += v.w;
        if (j == CH - 1 || codes[j + 1] != codes[j]) {
            float* es = g_embed_sum + (size_t)codes[j] * D + t * 4;
            atomicAdd(es + 0, acc.x);
            atomicAdd(es + 1, acc.y);
            atomicAdd(es + 2, acc.z);
            atomicAdd(es + 3, acc.w);
            acc = make_float4(0.f, 0.f, 0.f, 0.f);
        }
    }
}

// ---------------- #8 EMA embed (flat) ----------------
__global__ void __launch_bounds__(256) ema_embed(const float* __restrict__ embed_avg,
                                                 float* __restrict__ nea_out,
                                                 float* __restrict__ ne_out) {
    int i = blockIdx.x * 256 + threadIdx.x;   // over KCODES*D/4 float4
    int c = (i * 4) >> 9;
    float4 es = *((const float4*)g_embed_sum + i);
    float4 ea = __ldg((const float4*)embed_avg + i);
    float inv = 1.0f / g_cs[c];
    float4 nea, ne;
    nea.x = ea.x * DECAY + ONE_MINUS_DECAY * es.x; ne.x = nea.x * inv;
    nea.y = ea.y * DECAY + ONE_MINUS_DECAY * es.y; ne.y = nea.y * inv;
    nea.z = ea.z * DECAY + ONE_MINUS_DECAY * es.z; ne.z = nea.z * inv;
    nea.w = ea.w * DECAY + ONE_MINUS_DECAY * es.w; ne.w = nea.w * inv;
    ((float4*)nea_out)[i] = nea;
    ((float4*)ne_out)[i] = ne;
}

// ---------------- launch ----------------
extern "C" void kernel_launch(void* const* d_in, const int* in_sizes, int n_in,
                              void* d_out, int out_size) {
    const float* x = (const float*)d_in[0];
    const float* embed = (const float*)d_in[1];
    const float* cluster_size = (const float*)d_in[2];
    const float* embed_avg = (const float*)d_in[3];

    float* out = (float*)d_out;
    float* quant = out;
    float* eind  = quant + (size_t)NROWS * D;
    float* ncs   = eind + NROWS;
    float* nea   = ncs + KCODES;
    float* ne    = nea + (size_t)KCODES * D;

    cudaFuncSetAttribute(gemm_hmma, cudaFuncAttributeMaxDynamicSharedMemorySize, SMEM_TOTAL);

    prep_b<<<KCODES, 256>>>(embed);                      // #1
    convert_x<<<2048, 256>>>(x);                         // #2
    gemm_hmma<<<ROWTILES, 256, SMEM_TOTAL>>>(eind);      // #3
    rescue<<<2048, 256>>>(x, embed);                     // #4  <-- profile target
    scan_counts<<<1, 1024>>>(cluster_size, ncs, eind);   // #5
    fill_rowlist<<<NROWS / 256, 256>>>();                // #6
    seg_quant<<<NROWS / CH, 128>>>(x, embed, quant);     // #7
    ema_embed<<<KCODES * D / 4 / 256, 256>>>(embed_avg, nea, ne);  // #8
}

// round 16
// speedup vs baseline: 1.1145x; 1.0226x over previous
#include <cuda_runtime.h>
#include <cuda_fp16.h>
#include <cstdint>

#define DECAY 0.99f
#define ONE_MINUS_DECAY 0.01f
#define EPSF 1e-5f
#define D 512
#define KCODES 1024
#define NROWS 65536
#define BM 64
#define ROWTILES (NROWS / BM)    // 1024
#define NTILES 64                // 8 n-chunks * 8 k-tiles (BK=64)
#define B_BYTES 16384            // 128x64 fp16 per stage
#define B_STAGES 3
#define SMEM_B_OFF 65536         // A persistent region = 64KB
#define SMEM_TOTAL (SMEM_B_OFF + B_STAGES * B_BYTES)   // 114688
#define MARGIN 0.05f
#define CH 64                    // rowlist entries per seg block
#define RG 4                     // rescue rows per group

// ---------------- device scratch ----------------
__device__ unsigned g_bhi[KCODES * D / 2];    // fp16 pairs
__device__ float g_e2h[KCODES];   // 0.5*|e|^2
__device__ float g_embed_sum[KCODES * D];
__device__ int   g_ind[NROWS];
__device__ float g_cs[KCODES];
__device__ int   g_flag[NROWS];
__device__ int   g_nflag;
__device__ int   g_cnt[KCODES];
__device__ int   g_off[KCODES];
__device__ int   g_poslist[NROWS];
__device__ int   g_rowlist[NROWS];
__device__ unsigned long long g_best[NROWS];

// ---------------- PTX helpers ----------------
__device__ __forceinline__ uint32_t smem_u32(const void* p) {
    uint32_t a;
    asm("{ .reg .u64 t; cvta.to.shared.u64 t, %1; cvt.u32.u64 %0, t; }" : "=r"(a) : "l"(p));
    return a;
}
#define CP_ASYNC16(soff, gptr) \
    asm volatile("cp.async.cg.shared.global [%0], [%1], 16;" \
                 :: "r"(soff), "l"(__cvta_generic_to_global(gptr)))
#define CP_COMMIT() asm volatile("cp.async.commit_group;" ::: "memory")
#define CP_WAIT1() asm volatile("cp.async.wait_group 1;" ::: "memory")

#define LDMX4(r, addr) \
    asm volatile("ldmatrix.sync.aligned.m8n8.x4.shared.b16 {%0,%1,%2,%3}, [%4];" \
                 : "=r"((r)[0]), "=r"((r)[1]), "=r"((r)[2]), "=r"((r)[3]) : "r"(addr))

#define MMA_F16(c, a, b0, b1) \
    asm volatile("mma.sync.aligned.m16n8k16.row.col.f32.f16.f16.f32 " \
                 "{%0,%1,%2,%3}, {%4,%5,%6,%7}, {%8,%9}, {%0,%1,%2,%3};" \
                 : "+f"((c)[0]), "+f"((c)[1]), "+f"((c)[2]), "+f"((c)[3]) \
                 : "r"((a)[0]), "r"((a)[1]), "r"((a)[2]), "r"((a)[3]), "r"(b0), "r"(b1))

__device__ __forceinline__ unsigned pack2h(float a, float b) {
    __half2 h = __floats2half2_rn(a, b);
    return *(unsigned*)&h;
}

// ---------------- #1/#2 zero scratch (two halves so gemm is launch #4) ----------------
__global__ void zero_es(int half) {
    int i = blockIdx.x * blockDim.x + threadIdx.x + half * (KCODES * D / 2);
    g_embed_sum[i] = 0.0f;
    if (half == 1 && i < KCODES * D / 2 + KCODES) g_cnt[i - KCODES * D / 2] = 0;
    if (half == 1 && i == KCODES * D / 2) g_nflag = 0;
}

// ---------------- #3 prep B: convert embed fp16 + e2h ----------------
__global__ void prep_b(const float* __restrict__ embed) {
    int k = blockIdx.x;
    int t = threadIdx.x;       // 256 threads, one float2 each
    float2 v = *(const float2*)(embed + (size_t)k * D + t * 2);
    g_bhi[k * 256 + t] = pack2h(v.x, v.y);
    float s = v.x * v.x + v.y * v.y;
#pragma unroll
    for (int off = 16; off; off >>= 1) s += __shfl_down_sync(0xffffffffu, s, off);
    __shared__ float sh[8];
    if ((t & 31) == 0) sh[t >> 5] = s;
    __syncthreads();
    if (t == 0) {
        float tot = 0.0f;
#pragma unroll
        for (int i = 0; i < 8; i++) tot += sh[i];
        g_e2h[k] = 0.5f * tot;
    }
}

// ---------------- #4 HMMA GEMM: persistent fp16 A (converted in prologue), B-only staging ----
__global__ void __launch_bounds__(256, 2) gemm_hmma(const float* __restrict__ x,
                                                    float* __restrict__ eind) {
    extern __shared__ char smem[];
    uint32_t sb = smem_u32(smem);
    const int tid = threadIdx.x;
    const int lane = tid & 31;
    const int warpM = (tid >> 5) >> 2;   // 0..1
    const int warpN = (tid >> 5) & 3;    // 0..3
    const int gid = lane >> 2, tig = lane & 3;
    const int rowTile = blockIdx.x;

    float acc[2][4][4];
    float best[4], second[4];
    int bidx[4];
#pragma unroll
    for (int s = 0; s < 4; s++) { best[s] = -3.4e38f; second[s] = -3.4e38f; bidx[s] = 0; }

    auto issueB = [&](int t) {
        int nc = t >> 3, kt = t & 7;
        uint32_t st = sb + SMEM_B_OFF + (t % B_STAGES) * B_BYTES;
#pragma unroll
        for (int i = 0; i < 4; i++) {
            int idx = tid + i * 256;           // 0..1023
            int row = idx >> 3, g = idx & 7;
            uint32_t soff = st + row * 128 + ((g ^ (row & 7)) << 4);
            size_t goff = ((size_t)(nc * 128 + row) * D + kt * 64 + g * 8) >> 1;
            CP_ASYNC16(soff, g_bhi + goff);
        }
        CP_COMMIT();
    };

    issueB(0); issueB(1);

    // A prologue: load x fp32 once, convert fp16, store swizzled (8 regions by kt)
    {
        const float* xrow = x + (size_t)rowTile * BM * D;
        for (int gi = tid; gi < 4096; gi += 256) {   // 8-float groups
            int r = gi >> 6;            // row 0..63
            int c0 = (gi & 63) * 8;     // col 0..504
            int kt = c0 >> 6;
            int g = (c0 & 63) >> 3;     // 16B chunk within 128B row
            float4 v0 = __ldg((const float4*)(xrow + (size_t)r * D + c0));
            float4 v1 = __ldg((const float4*)(xrow + (size_t)r * D + c0 + 4));
            uint4 u;
            u.x = pack2h(v0.x, v0.y); u.y = pack2h(v0.z, v0.w);
            u.z = pack2h(v1.x, v1.y); u.w = pack2h(v1.z, v1.w);
            *(uint4*)(smem + kt * 8192 + r * 128 + ((g ^ (r & 7)) << 4)) = u;
        }
    }

    for (int t = 0; t < NTILES; t++) {
        CP_WAIT1();
        __syncthreads();   // also guards A-prologue writes at t=0
        if (t + 2 < NTILES) issueB(t + 2); else CP_COMMIT();

        if ((t & 7) == 0) {
#pragma unroll
            for (int m = 0; m < 2; m++)
#pragma unroll
                for (int n = 0; n < 4; n++)
#pragma unroll
                    for (int j = 0; j < 4; j++) acc[m][n][j] = 0.0f;
        }

        int kt = t & 7;
        uint32_t stA = sb + kt * 8192;
        uint32_t stB = sb + SMEM_B_OFF + (t % B_STAGES) * B_BYTES;
#pragma unroll
        for (int ks = 0; ks < 4; ks++) {
            uint32_t ah[2][4], bh[2][4];
#pragma unroll
            for (int m = 0; m < 2; m++) {
                int r = warpM * 32 + m * 16 + (lane & 15);
                int kc = ks * 2 + (lane >> 4);
                uint32_t a = stA + r * 128 + ((kc ^ (r & 7)) << 4);
                LDMX4(ah[m], a);
            }
#pragma unroll
            for (int p = 0; p < 2; p++) {
                int grp = lane >> 3;
                int nt = p * 2 + (grp >> 1);
                int kc = ks * 2 + (grp & 1);
                int r = warpN * 32 + nt * 8 + (lane & 7);
                uint32_t a = stB + r * 128 + ((kc ^ (r & 7)) << 4);
                LDMX4(bh[p], a);
            }
#pragma unroll
            for (int m = 0; m < 2; m++)
#pragma unroll
                for (int n = 0; n < 4; n++) {
                    uint32_t b0h = bh[n >> 1][(n & 1) * 2], b1h = bh[n >> 1][(n & 1) * 2 + 1];
                    MMA_F16(acc[m][n], ah[m], b0h, b1h);
                }
        }

        if ((t & 7) == 7) {
            int nc = t >> 3;
#pragma unroll
            for (int n = 0; n < 4; n++) {
                int col0 = nc * 128 + warpN * 32 + n * 8 + tig * 2;
                float e0 = __ldg(&g_e2h[col0]);
                float e1 = __ldg(&g_e2h[col0 + 1]);
#pragma unroll
                for (int m = 0; m < 2; m++)
#pragma unroll
                    for (int h = 0; h < 2; h++) {
                        int slot = m * 2 + h;
                        float s0 = acc[m][n][h * 2 + 0] - e0;
                        float s1 = acc[m][n][h * 2 + 1] - e1;
                        if (s0 > best[slot]) { second[slot] = best[slot]; best[slot] = s0; bidx[slot] = col0; }
                        else if (s0 > second[slot]) second[slot] = s0;
                        if (s1 > best[slot]) { second[slot] = best[slot]; best[slot] = s1; bidx[slot] = col0 + 1; }
                        else if (s1 > second[slot]) second[slot] = s1;
                    }
            }
        }
    }

    __syncthreads();
    float* mb = (float*)smem;          // reuse A region
    float* ms = mb + 256;
    int*   mi = (int*)(ms + 256);
#pragma unroll
    for (int slot = 0; slot < 4; slot++) {
        float b = best[slot], s = second[slot];
        int i = bidx[slot];
#pragma unroll
        for (int off = 1; off <= 2; off <<= 1) {
            float ob = __shfl_xor_sync(0xffffffffu, b, off);
            float os = __shfl_xor_sync(0xffffffffu, s, off);
            int   oi = __shfl_xor_sync(0xffffffffu, i, off);
            if (ob > b || (ob == b && oi < i)) { s = fmaxf(os, b); b = ob; i = oi; }
            else s = fmaxf(s, ob);
        }
        if (tig == 0) {
            int row = warpM * 32 + (slot >> 1) * 16 + gid + (slot & 1) * 8;
            mb[row * 4 + warpN] = b; ms[row * 4 + warpN] = s; mi[row * 4 + warpN] = i;
        }
    }
    __syncthreads();
    if (tid < BM) {
        int row = tid;
        float b = mb[row * 4], s = ms[row * 4];
        int i = mi[row * 4];
#pragma unroll
        for (int w = 1; w < 4; w++) {
            float ob = mb[row * 4 + w], os = ms[row * 4 + w];
            int oi = mi[row * 4 + w];
            if (ob > b || (ob == b && oi < i)) { s = fmaxf(os, b); b = ob; i = oi; }
            else s = fmaxf(s, ob);
        }
        int grow = rowTile * BM + row;
        g_ind[grow] = i;
        if (b - s < MARGIN) {
            g_best[grow] = 0ull;
            int p = atomicAdd(&g_nflag, 1);
            g_flag[p] = grow;
        } else {
            g_poslist[grow] = atomicAdd(&g_cnt[i], 1);
            eind[grow] = (float)i;
        }
    }
}

// ---------------- #5 exact fp32 rescue: one item = (4-row group, 1/8 codebook) ----------------
__global__ void __launch_bounds__(256) rescue(const float* __restrict__ x,
                                              const float* __restrict__ embed) {
    __shared__ float4 xs[RG][128];     // 4 rows x 512 floats = 8KB
    int tid = threadIdx.x;
    int w = tid >> 5, lane = tid & 31;
    int nf = g_nflag;
    int nitems = ((nf + RG - 1) / RG) * 8;
    for (int it = blockIdx.x; it < nitems; it += gridDim.x) {
        int g = it >> 3, slice = it & 7;
        int cnt = min(RG, nf - g * RG);
        __syncthreads();
        for (int i = tid; i < cnt * 128; i += 256) {
            int r = i >> 7, j = i & 127;
            xs[r][j] = *((const float4*)(x + (size_t)g_flag[g * RG + r] * D) + j);
        }
        __syncthreads();
        float best = -3.4e38f;
        int bc = 0;
#pragma unroll
        for (int i = 0; i < 16; i++) {
            int c = slice * 128 + w * 16 + i;
            const float4* ep = (const float4*)(embed + (size_t)c * D);
            float acc[RG];
#pragma unroll
            for (int r = 0; r < RG; r++) acc[r] = 0.0f;
#pragma unroll
            for (int p = 0; p < 4; p++) {
                float4 e = __ldg(ep + lane + p * 32);
#pragma unroll
                for (int r = 0; r < RG; r++) {
                    float4 xv = xs[r][lane + p * 32];
                    acc[r] = fmaf(xv.x, e.x, fmaf(xv.y, e.y,
                              fmaf(xv.z, e.z, fmaf(xv.w, e.w, acc[r]))));
                }
            }
#pragma unroll
            for (int r = 0; r < RG; r++) {
#pragma unroll
                for (int off = 16; off; off >>= 1)
                    acc[r] += __shfl_xor_sync(0xffffffffu, acc[r], off);
            }
            if (lane < cnt) {
                float s = acc[lane] - g_e2h[c];
                if (s > best) { best = s; bc = c; }
            }
        }
        if (lane < cnt) {
            unsigned bits = __float_as_uint(best);
            unsigned mono = (bits & 0x80000000u) ? ~bits : (bits | 0x80000000u);
            unsigned long long u = ((unsigned long long)mono << 32) | (unsigned)(~bc);
            atomicMax(&g_best[g_flag[g * RG + lane]], u);
        }
    }
}

// ---------------- #6 rescue finalize + scan + ema_cs (single block) ----------------
__global__ void scan_counts(const float* __restrict__ cluster_size,
                            float* __restrict__ ncs_out,
                            float* __restrict__ eind) {
    int k = threadIdx.x;
    int nf = g_nflag;
    for (int i = k; i < nf; i += 1024) {
        int row = g_flag[i];
        int kk = (int)(~(unsigned)(g_best[row] & 0xffffffffull)) & 1023;
        g_ind[row] = kk;
        g_poslist[row] = atomicAdd(&g_cnt[kk], 1);
        eind[row] = (float)kk;
    }
    __syncthreads();
    __shared__ int s[1024];
    __shared__ float f[1024];
    int my = g_cnt[k];
    s[k] = my;
    __syncthreads();
#pragma unroll
    for (int off = 1; off < 1024; off <<= 1) {
        int v = (k >= off) ? s[k - off] : 0;
        __syncthreads();
        s[k] += v;
        __syncthreads();
    }
    g_off[k] = s[k] - my;
    float ncs = cluster_size[k] * DECAY + ONE_MINUS_DECAY * (float)my;
    ncs_out[k] = ncs;
    f[k] = ncs;
    __syncthreads();
#pragma unroll
    for (int st = 512; st > 0; st >>= 1) {
        if (k < st) f[k] += f[k + st];
        __syncthreads();
    }
    float n = f[0];
    g_cs[k] = (ncs + EPSF) / (n + (float)KCODES * EPSF) * n;
}

// ---------------- #7 fill rowlist ----------------
__global__ void fill_rowlist() {
    int row = blockIdx.x * blockDim.x + threadIdx.x;
    int k = g_ind[row];
    g_rowlist[g_off[k] + g_poslist[row]] = row;
}

// ---------------- #8 seg_quant: quant fill + segmented embed_sum fused ----------------
__global__ void __launch_bounds__(128) seg_quant(const float* __restrict__ x,
                                                 const float* __restrict__ embed,
                                                 float* __restrict__ quant) {
    __shared__ int rows[CH];
    __shared__ int codes[CH];
    int t = threadIdx.x;
    int j0 = blockIdx.x * CH;
    if (t < CH) {
        int r = g_rowlist[j0 + t];
        rows[t] = r;
        codes[t] = g_ind[r];
    }
    __syncthreads();
    float4 e = __ldg((const float4*)(embed + (size_t)codes[0] * D) + t);
    float4 acc = {0.f, 0.f, 0.f, 0.f};
#pragma unroll 4
    for (int j = 0; j < CH; j++) {
        if (j > 0 && codes[j] != codes[j - 1])
            e = __ldg((const float4*)(embed + (size_t)codes[j] * D) + t);
        *((float4*)(quant + (size_t)rows[j] * D) + t) = e;
        float4 v = __ldg((const float4*)(x + (size_t)rows[j] * D) + t);
        acc.x += v.x; acc.y += v.y; acc.z += v.z; acc.w += v.w;
        if (j == CH - 1 || codes[j + 1] != codes[j]) {
            float* es = g_embed_sum + (size_t)codes[j] * D + t * 4;
            atomicAdd(es + 0, acc.x);
            atomicAdd(es + 1, acc.y);
            atomicAdd(es + 2, acc.z);
            atomicAdd(es + 3, acc.w);
            acc = make_float4(0.f, 0.f, 0.f, 0.f);
        }
    }
}

// ---------------- #9 EMA embed (flat) ----------------
__global__ void __launch_bounds__(256) ema_embed(const float* __restrict__ embed_avg,
                                                 float* __restrict__ nea_out,
                                                 float* __restrict__ ne_out) {
    int i = blockIdx.x * 256 + threadIdx.x;   // over KCODES*D/4 float4
    int c = (i * 4) >> 9;
    float4 es = *((const float4*)g_embed_sum + i);
    float4 ea = __ldg((const float4*)embed_avg + i);
    float inv = 1.0f / g_cs[c];
    float4 nea, ne;
    nea.x = ea.x * DECAY + ONE_MINUS_DECAY * es.x; ne.x = nea.x * inv;
    nea.y = ea.y * DECAY + ONE_MINUS_DECAY * es.y; ne.y = nea.y * inv;
    nea.z = ea.z * DECAY + ONE_MINUS_DECAY * es.z; ne.z = nea.z * inv;
    nea.w = ea.w * DECAY + ONE_MINUS_DECAY * es.w; ne.w = nea.w * inv;
    ((float4*)nea_out)[i] = nea;
    ((float4*)ne_out)[i] = ne;
}

// ---------------- launch ----------------
extern "C" void kernel_launch(void* const* d_in, const int* in_sizes, int n_in,
                              void* d_out, int out_size) {
    const float* x = (const float*)d_in[0];
    const float* embed = (const float*)d_in[1];
    const float* cluster_size = (const float*)d_in[2];
    const float* embed_avg = (const float*)d_in[3];

    float* out = (float*)d_out;
    float* quant = out;
    float* eind  = quant + (size_t)NROWS * D;
    float* ncs   = eind + NROWS;
    float* nea   = ncs + KCODES;
    float* ne    = nea + (size_t)KCODES * D;

    cudaFuncSetAttribute(gemm_hmma, cudaFuncAttributeMaxDynamicSharedMemorySize, SMEM_TOTAL);

    zero_es<<<KCODES * D / 2 / 256, 256>>>(0);           // #1
    zero_es<<<KCODES * D / 2 / 256, 256>>>(1);           // #2
    prep_b<<<KCODES, 256>>>(embed);                      // #3
    gemm_hmma<<<ROWTILES, 256, SMEM_TOTAL>>>(x, eind);   // #4  <-- profile target
    rescue<<<2048, 256>>>(x, embed);                     // #5
    scan_counts<<<1, 1024>>>(cluster_size, ncs, eind);   // #6
    fill_rowlist<<<NROWS / 256, 256>>>();                // #7
    seg_quant<<<NROWS / CH, 128>>>(x, embed, quant);     // #8
    ema_embed<<<KCODES * D / 4 / 256, 256>>>(embed_avg, nea, ne);  // #9
}

// round 17
// speedup vs baseline: 1.1234x; 1.0080x over previous
#include <cuda_runtime.h>
#include <cuda_fp16.h>
#include <cstdint>

#define DECAY 0.99f
#define ONE_MINUS_DECAY 0.01f
#define EPSF 1e-5f
#define D 512
#define KCODES 1024
#define NROWS 65536
#define BM 64
#define ROWTILES (NROWS / BM)    // 1024
#define NTILES 64                // 8 n-chunks * 8 k-tiles (BK=64)
#define B_BYTES 16384            // 128x64 fp16 per stage
#define B_STAGES 3
#define SMEM_B_OFF 65536         // A persistent region = 64KB
#define SMEM_TOTAL (SMEM_B_OFF + B_STAGES * B_BYTES)   // 114688
#define MARGIN 0.05f
#define CH 64                    // rowlist entries per seg block
#define RG 4                     // rescue rows per group

// ---------------- device scratch ----------------
__device__ unsigned g_bhi[KCODES * D / 2];    // fp16 pairs
__device__ float g_e2h[KCODES];   // 0.5*|e|^2
__device__ float g_embed_sum[KCODES * D];
__device__ int   g_ind[NROWS];
__device__ float g_cs[KCODES];
__device__ int   g_flag[NROWS];
__device__ int   g_nflag;
__device__ int   g_cnt[KCODES];
__device__ int   g_off[KCODES];
__device__ int   g_poslist[NROWS];
__device__ int   g_rowlist[NROWS];
__device__ unsigned long long g_best[NROWS];

// ---------------- PTX helpers ----------------
__device__ __forceinline__ uint32_t smem_u32(const void* p) {
    uint32_t a;
    asm("{ .reg .u64 t; cvta.to.shared.u64 t, %1; cvt.u32.u64 %0, t; }" : "=r"(a) : "l"(p));
    return a;
}
#define CP_ASYNC16(soff, gptr) \
    asm volatile("cp.async.cg.shared.global [%0], [%1], 16;" \
                 :: "r"(soff), "l"(__cvta_generic_to_global(gptr)))
#define CP_COMMIT() asm volatile("cp.async.commit_group;" ::: "memory")
#define CP_WAIT1() asm volatile("cp.async.wait_group 1;" ::: "memory")

#define LDMX4(r, addr) \
    asm volatile("ldmatrix.sync.aligned.m8n8.x4.shared.b16 {%0,%1,%2,%3}, [%4];" \
                 : "=r"((r)[0]), "=r"((r)[1]), "=r"((r)[2]), "=r"((r)[3]) : "r"(addr))

#define MMA_F16(c, a, b0, b1) \
    asm volatile("mma.sync.aligned.m16n8k16.row.col.f32.f16.f16.f32 " \
                 "{%0,%1,%2,%3}, {%4,%5,%6,%7}, {%8,%9}, {%0,%1,%2,%3};" \
                 : "+f"((c)[0]), "+f"((c)[1]), "+f"((c)[2]), "+f"((c)[3]) \
                 : "r"((a)[0]), "r"((a)[1]), "r"((a)[2]), "r"((a)[3]), "r"(b0), "r"(b1))

__device__ __forceinline__ unsigned pack2h(float a, float b) {
    __half2 h = __floats2half2_rn(a, b);
    return *(unsigned*)&h;
}

// ---------------- #1 prep: convert embed fp16 + e2h + zero embed_sum/cnt/nflag -------------
__global__ void prep_b(const float* __restrict__ embed) {
    int k = blockIdx.x;
    int t = threadIdx.x;       // 256 threads, one float2 each
    if (t == 0) g_cnt[k] = 0;
    if (k == 0 && t == 1) g_nflag = 0;
    ((float2*)g_embed_sum)[k * 256 + t] = make_float2(0.f, 0.f);
    float2 v = *(const float2*)(embed + (size_t)k * D + t * 2);
    g_bhi[k * 256 + t] = pack2h(v.x, v.y);
    float s = v.x * v.x + v.y * v.y;
#pragma unroll
    for (int off = 16; off; off >>= 1) s += __shfl_down_sync(0xffffffffu, s, off);
    __shared__ float sh[8];
    if ((t & 31) == 0) sh[t >> 5] = s;
    __syncthreads();
    if (t == 0) {
        float tot = 0.0f;
#pragma unroll
        for (int i = 0; i < 8; i++) tot += sh[i];
        g_e2h[k] = 0.5f * tot;
    }
}

// ---------------- #2 HMMA GEMM: persistent fp16 A (converted in prologue), B-only staging ----
__global__ void __launch_bounds__(256, 2) gemm_hmma(const float* __restrict__ x,
                                                    float* __restrict__ eind) {
    extern __shared__ char smem[];
    uint32_t sb = smem_u32(smem);
    const int tid = threadIdx.x;
    const int lane = tid & 31;
    const int warpM = (tid >> 5) >> 2;   // 0..1
    const int warpN = (tid >> 5) & 3;    // 0..3
    const int gid = lane >> 2, tig = lane & 3;
    const int rowTile = blockIdx.x;

    float acc[2][4][4];
    float best[4], second[4];
    int bidx[4];
#pragma unroll
    for (int s = 0; s < 4; s++) { best[s] = -3.4e38f; second[s] = -3.4e38f; bidx[s] = 0; }

    auto issueB = [&](int t) {
        int nc = t >> 3, kt = t & 7;
        uint32_t st = sb + SMEM_B_OFF + (t % B_STAGES) * B_BYTES;
#pragma unroll
        for (int i = 0; i < 4; i++) {
            int idx = tid + i * 256;           // 0..1023
            int row = idx >> 3, g = idx & 7;
            uint32_t soff = st + row * 128 + ((g ^ (row & 7)) << 4);
            size_t goff = ((size_t)(nc * 128 + row) * D + kt * 64 + g * 8) >> 1;
            CP_ASYNC16(soff, g_bhi + goff);
        }
        CP_COMMIT();
    };

    issueB(0); issueB(1);

    // A prologue: load x fp32 once, convert fp16, store swizzled (8 regions by kt)
    {
        const float* xrow = x + (size_t)rowTile * BM * D;
        for (int gi = tid; gi < 4096; gi += 256) {   // 8-float groups
            int r = gi >> 6;            // row 0..63
            int c0 = (gi & 63) * 8;     // col 0..504
            int kt = c0 >> 6;
            int g = (c0 & 63) >> 3;     // 16B chunk within 128B row
            float4 v0 = __ldg((const float4*)(xrow + (size_t)r * D + c0));
            float4 v1 = __ldg((const float4*)(xrow + (size_t)r * D + c0 + 4));
            uint4 u;
            u.x = pack2h(v0.x, v0.y); u.y = pack2h(v0.z, v0.w);
            u.z = pack2h(v1.x, v1.y); u.w = pack2h(v1.z, v1.w);
            *(uint4*)(smem + kt * 8192 + r * 128 + ((g ^ (r & 7)) << 4)) = u;
        }
    }

    for (int t = 0; t < NTILES; t++) {
        CP_WAIT1();
        __syncthreads();   // also guards A-prologue writes at t=0
        if (t + 2 < NTILES) issueB(t + 2); else CP_COMMIT();

        if ((t & 7) == 0) {
#pragma unroll
            for (int m = 0; m < 2; m++)
#pragma unroll
                for (int n = 0; n < 4; n++)
#pragma unroll
                    for (int j = 0; j < 4; j++) acc[m][n][j] = 0.0f;
        }

        int kt = t & 7;
        uint32_t stA = sb + kt * 8192;
        uint32_t stB = sb + SMEM_B_OFF + (t % B_STAGES) * B_BYTES;
#pragma unroll
        for (int ks = 0; ks < 4; ks++) {
            uint32_t ah[2][4], bh[2][4];
#pragma unroll
            for (int m = 0; m < 2; m++) {
                int r = warpM * 32 + m * 16 + (lane & 15);
                int kc = ks * 2 + (lane >> 4);
                uint32_t a = stA + r * 128 + ((kc ^ (r & 7)) << 4);
                LDMX4(ah[m], a);
            }
#pragma unroll
            for (int p = 0; p < 2; p++) {
                int grp = lane >> 3;
                int nt = p * 2 + (grp >> 1);
                int kc = ks * 2 + (grp & 1);
                int r = warpN * 32 + nt * 8 + (lane & 7);
                uint32_t a = stB + r * 128 + ((kc ^ (r & 7)) << 4);
                LDMX4(bh[p], a);
            }
#pragma unroll
            for (int m = 0; m < 2; m++)
#pragma unroll
                for (int n = 0; n < 4; n++) {
                    uint32_t b0h = bh[n >> 1][(n & 1) * 2], b1h = bh[n >> 1][(n & 1) * 2 + 1];
                    MMA_F16(acc[m][n], ah[m], b0h, b1h);
                }
        }

        if ((t & 7) == 7) {
            int nc = t >> 3;
#pragma unroll
            for (int n = 0; n < 4; n++) {
                int col0 = nc * 128 + warpN * 32 + n * 8 + tig * 2;
                float e0 = __ldg(&g_e2h[col0]);
                float e1 = __ldg(&g_e2h[col0 + 1]);
#pragma unroll
                for (int m = 0; m < 2; m++)
#pragma unroll
                    for (int h = 0; h < 2; h++) {
                        int slot = m * 2 + h;
                        float s0 = acc[m][n][h * 2 + 0] - e0;
                        float s1 = acc[m][n][h * 2 + 1] - e1;
                        if (s0 > best[slot]) { second[slot] = best[slot]; best[slot] = s0; bidx[slot] = col0; }
                        else if (s0 > second[slot]) second[slot] = s0;
                        if (s1 > best[slot]) { second[slot] = best[slot]; best[slot] = s1; bidx[slot] = col0 + 1; }
                        else if (s1 > second[slot]) second[slot] = s1;
                    }
            }
        }
    }

    __syncthreads();
    float* mb = (float*)smem;          // reuse A region
    float* ms = mb + 256;
    int*   mi = (int*)(ms + 256);
#pragma unroll
    for (int slot = 0; slot < 4; slot++) {
        float b = best[slot], s = second[slot];
        int i = bidx[slot];
#pragma unroll
        for (int off = 1; off <= 2; off <<= 1) {
            float ob = __shfl_xor_sync(0xffffffffu, b, off);
            float os = __shfl_xor_sync(0xffffffffu, s, off);
            int   oi = __shfl_xor_sync(0xffffffffu, i, off);
            if (ob > b || (ob == b && oi < i)) { s = fmaxf(os, b); b = ob; i = oi; }
            else s = fmaxf(s, ob);
        }
        if (tig == 0) {
            int row = warpM * 32 + (slot >> 1) * 16 + gid + (slot & 1) * 8;
            mb[row * 4 + warpN] = b; ms[row * 4 + warpN] = s; mi[row * 4 + warpN] = i;
        }
    }
    __syncthreads();
    if (tid < BM) {
        int row = tid;
        float b = mb[row * 4], s = ms[row * 4];
        int i = mi[row * 4];
#pragma unroll
        for (int w = 1; w < 4; w++) {
            float ob = mb[row * 4 + w], os = ms[row * 4 + w];
            int oi = mi[row * 4 + w];
            if (ob > b || (ob == b && oi < i)) { s = fmaxf(os, b); b = ob; i = oi; }
            else s = fmaxf(s, ob);
        }
        int grow = rowTile * BM + row;
        g_ind[grow] = i;
        if (b - s < MARGIN) {
            g_best[grow] = 0ull;
            int p = atomicAdd(&g_nflag, 1);
            g_flag[p] = grow;
        } else {
            g_poslist[grow] = atomicAdd(&g_cnt[i], 1);
            eind[grow] = (float)i;
        }
    }
}

// ---------------- #3 exact fp32 rescue: one item = (4-row group, 1/8 codebook) ----------------
__global__ void __launch_bounds__(256) rescue(const float* __restrict__ x,
                                              const float* __restrict__ embed) {
    __shared__ float4 xs[RG][128];     // 4 rows x 512 floats = 8KB
    int tid = threadIdx.x;
    int w = tid >> 5, lane = tid & 31;
    int nf = g_nflag;
    int nitems = ((nf + RG - 1) / RG) * 8;
    for (int it = blockIdx.x; it < nitems; it += gridDim.x) {
        int g = it >> 3, slice = it & 7;
        int cnt = min(RG, nf - g * RG);
        __syncthreads();
        for (int i = tid; i < cnt * 128; i += 256) {
            int r = i >> 7, j = i & 127;
            xs[r][j] = *((const float4*)(x + (size_t)g_flag[g * RG + r] * D) + j);
        }
        __syncthreads();
        float best = -3.4e38f;
        int bc = 0;
#pragma unroll
        for (int i = 0; i < 16; i++) {
            int c = slice * 128 + w * 16 + i;
            const float4* ep = (const float4*)(embed + (size_t)c * D);
            float acc[RG];
#pragma unroll
            for (int r = 0; r < RG; r++) acc[r] = 0.0f;
#pragma unroll
            for (int p = 0; p < 4; p++) {
                float4 e = __ldg(ep + lane + p * 32);
#pragma unroll
                for (int r = 0; r < RG; r++) {
                    float4 xv = xs[r][lane + p * 32];
                    acc[r] = fmaf(xv.x, e.x, fmaf(xv.y, e.y,
                              fmaf(xv.z, e.z, fmaf(xv.w, e.w, acc[r]))));
                }
            }
#pragma unroll
            for (int r = 0; r < RG; r++) {
#pragma unroll
                for (int off = 16; off; off >>= 1)
                    acc[r] += __shfl_xor_sync(0xffffffffu, acc[r], off);
            }
            if (lane < cnt) {
                float s = acc[lane] - g_e2h[c];
                if (s > best) { best = s; bc = c; }
            }
        }
        if (lane < cnt) {
            unsigned bits = __float_as_uint(best);
            unsigned mono = (bits & 0x80000000u) ? ~bits : (bits | 0x80000000u);
            unsigned long long u = ((unsigned long long)mono << 32) | (unsigned)(~bc);
            atomicMax(&g_best[g_flag[g * RG + lane]], u);
        }
    }
}

// ---------------- #4 rescue finalize + scan + ema_cs (single block) <-- profiled ----------------
__global__ void scan_counts(const float* __restrict__ cluster_size,
                            float* __restrict__ ncs_out,
                            float* __restrict__ eind) {
    int k = threadIdx.x;
    int nf = g_nflag;
    for (int i = k; i < nf; i += 1024) {
        int row = g_flag[i];
        int kk = (int)(~(unsigned)(g_best[row] & 0xffffffffull)) & 1023;
        g_ind[row] = kk;
        g_poslist[row] = atomicAdd(&g_cnt[kk], 1);
        eind[row] = (float)kk;
    }
    __syncthreads();
    __shared__ int s[1024];
    __shared__ float f[1024];
    int my = g_cnt[k];
    s[k] = my;
    __syncthreads();
#pragma unroll
    for (int off = 1; off < 1024; off <<= 1) {
        int v = (k >= off) ? s[k - off] : 0;
        __syncthreads();
        s[k] += v;
        __syncthreads();
    }
    g_off[k] = s[k] - my;
    float ncs = cluster_size[k] * DECAY + ONE_MINUS_DECAY * (float)my;
    ncs_out[k] = ncs;
    f[k] = ncs;
    __syncthreads();
#pragma unroll
    for (int st = 512; st > 0; st >>= 1) {
        if (k < st) f[k] += f[k + st];
        __syncthreads();
    }
    float n = f[0];
    g_cs[k] = (ncs + EPSF) / (n + (float)KCODES * EPSF) * n;
}

// ---------------- #5 fill rowlist ----------------
__global__ void fill_rowlist() {
    int row = blockIdx.x * blockDim.x + threadIdx.x;
    int k = g_ind[row];
    g_rowlist[g_off[k] + g_poslist[row]] = row;
}

// ---------------- #6 seg_quant: quant fill + segmented embed_sum fused ----------------
__global__ void __launch_bounds__(128) seg_quant(const float* __restrict__ x,
                                                 const float* __restrict__ embed,
                                                 float* __restrict__ quant) {
    __shared__ int rows[CH];
    __shared__ int codes[CH];
    int t = threadIdx.x;
    int j0 = blockIdx.x * CH;
    if (t < CH) {
        int r = g_rowlist[j0 + t];
        rows[t] = r;
        codes[t] = g_ind[r];
    }
    __syncthreads();
    float4 e = __ldg((const float4*)(embed + (size_t)codes[0] * D) + t);
    float4 acc = {0.f, 0.f, 0.f, 0.f};
#pragma unroll 4
    for (int j = 0; j < CH; j++) {
        if (j > 0 && codes[j] != codes[j - 1])
            e = __ldg((const float4*)(embed + (size_t)codes[j] * D) + t);
        *((float4*)(quant + (size_t)rows[j] * D) + t) = e;
        float4 v = __ldg((const float4*)(x + (size_t)rows[j] * D) + t);
        acc.x += v.x; acc.y += v.y; acc.z += v.z; acc.w += v.w;
        if (j == CH - 1 || codes[j + 1] != codes[j]) {
            float* es = g_embed_sum + (size_t)codes[j] * D + t * 4;
            atomicAdd(es + 0, acc.x);
            atomicAdd(es + 1, acc.y);
            atomicAdd(es + 2, acc.z);
            atomicAdd(es + 3, acc.w);
            acc = make_float4(0.f, 0.f, 0.f, 0.f);
        }
    }
}

// ---------------- #7 EMA embed (flat) ----------------
__global__ void __launch_bounds__(256) ema_embed(const float* __restrict__ embed_avg,
                                                 float* __restrict__ nea_out,
                                                 float* __restrict__ ne_out) {
    int i = blockIdx.x * 256 + threadIdx.x;   // over KCODES*D/4 float4
    int c = (i * 4) >> 9;
    float4 es = *((const float4*)g_embed_sum + i);
    float4 ea = __ldg((const float4*)embed_avg + i);
    float inv = 1.0f / g_cs[c];
    float4 nea, ne;
    nea.x = ea.x * DECAY + ONE_MINUS_DECAY * es.x; ne.x = nea.x * inv;
    nea.y = ea.y * DECAY + ONE_MINUS_DECAY * es.y; ne.y = nea.y * inv;
    nea.z = ea.z * DECAY + ONE_MINUS_DECAY * es.z; ne.z = nea.z * inv;
    nea.w = ea.w * DECAY + ONE_MINUS_DECAY * es.w; ne.w = nea.w * inv;
    ((float4*)nea_out)[i] = nea;
    ((float4*)ne_out)[i] = ne;
}

// ---------------- launch ----------------
extern "C" void kernel_launch(void* const* d_in, const int* in_sizes, int n_in,
                              void* d_out, int out_size) {
    const float* x = (const float*)d_in[0];
    const float* embed = (const float*)d_in[1];
    const float* cluster_size = (const float*)d_in[2];
    const float* embed_avg = (const float*)d_in[3];

    float* out = (float*)d_out;
    float* quant = out;
    float* eind  = quant + (size_t)NROWS * D;
    float* ncs   = eind + NROWS;
    float* nea   = ncs + KCODES;
    float* ne    = nea + (size_t)KCODES * D;

    cudaFuncSetAttribute(gemm_hmma, cudaFuncAttributeMaxDynamicSharedMemorySize, SMEM_TOTAL);

    prep_b<<<KCODES, 256>>>(embed);                      // #1 (zero + convert + e2h)
    gemm_hmma<<<ROWTILES, 256, SMEM_TOTAL>>>(x, eind);   // #2
    rescue<<<4096, 256>>>(x, embed);                     // #3
    scan_counts<<<1, 1024>>>(cluster_size, ncs, eind);   // #4  <-- profile target
    fill_rowlist<<<NROWS / 256, 256>>>();                // #5
    seg_quant<<<NROWS / CH, 128>>>(x, embed, quant);     // #6
    ema_embed<<<KCODES * D / 4 / 256, 256>>>(embed_avg, nea, ne);  // #7
}